// round 13
// baseline (speedup 1.0000x reference)
#include <cuda_runtime.h>
#include <cuda_fp16.h>
#include <math.h>
#include <stdint.h>

#define S_LEN 2048
#define HID   2048
#define NH    32
#define NKV   8
#define HD    64

// ---------------------------------------------------------------------------
// Scratch (device globals)
// ---------------------------------------------------------------------------
__device__ __half g_Xh[S_LEN * HID], g_Xl[S_LEN * HID];   // X split (fp16 hi+lo)
__device__ __half g_Wq[HID * HID];                         // weights single fp16
__device__ __half g_Wk[NKV * HD * HID];
__device__ __half g_Wv[NKV * HD * HID];
__device__ __half g_Wo[HID * HID];
__device__ __half g_Ch[S_LEN * HID];                       // attn out single fp16

__device__ __half g_qh[NH * S_LEN * HD], g_ql[NH * S_LEN * HD];  // post-RoPE Q split
__device__ __half g_kh[NKV * S_LEN * HD];                        // K single fp16
__device__ __half g_vh[NKV * S_LEN * HD];                        // V single fp16

// ---------------------------------------------------------------------------
// PTX helpers
// ---------------------------------------------------------------------------
__device__ __forceinline__ uint32_t s2u(const void* p) {
    uint32_t a;
    asm("{ .reg .u64 t; cvta.to.shared.u64 t, %1; cvt.u32.u64 %0, t; }" : "=r"(a) : "l"(p));
    return a;
}

__device__ __forceinline__ void ldsm4(uint32_t* r, uint32_t addr) {
    asm volatile("ldmatrix.sync.aligned.m8n8.x4.shared.b16 {%0,%1,%2,%3}, [%4];"
                 : "=r"(r[0]), "=r"(r[1]), "=r"(r[2]), "=r"(r[3]) : "r"(addr));
}

__device__ __forceinline__ void ldsm4t(uint32_t* r, uint32_t addr) {
    asm volatile("ldmatrix.sync.aligned.m8n8.x4.trans.shared.b16 {%0,%1,%2,%3}, [%4];"
                 : "=r"(r[0]), "=r"(r[1]), "=r"(r[2]), "=r"(r[3]) : "r"(addr));
}

__device__ __forceinline__ void mma16816(float* d, uint32_t a0, uint32_t a1, uint32_t a2,
                                         uint32_t a3, uint32_t b0, uint32_t b1) {
    asm volatile(
        "mma.sync.aligned.m16n8k16.row.col.f32.f16.f16.f32 "
        "{%0,%1,%2,%3}, {%4,%5,%6,%7}, {%8,%9}, {%0,%1,%2,%3};"
        : "+f"(d[0]), "+f"(d[1]), "+f"(d[2]), "+f"(d[3])
        : "r"(a0), "r"(a1), "r"(a2), "r"(a3), "r"(b0), "r"(b1));
}

__device__ __forceinline__ void cpa16(uint32_t saddr, const void* g) {
    asm volatile("cp.async.cg.shared.global [%0], [%1], 16;" :: "r"(saddr), "l"(g) : "memory");
}

__device__ __forceinline__ uint32_t packhf(float lo, float hi) {
    uint32_t r;
    asm("cvt.rn.f16x2.f32 %0, %1, %2;" : "=r"(r) : "f"(hi), "f"(lo));
    return r;
}
__device__ __forceinline__ float lo_h(uint32_t p) {
    return __half2float(__ushort_as_half((unsigned short)(p & 0xFFFFu)));
}
__device__ __forceinline__ float hi_h(uint32_t p) {
    return __half2float(__ushort_as_half((unsigned short)(p >> 16)));
}

// ---------------------------------------------------------------------------
// Merged conversion: X -> fp16 hi/lo split; weights -> single fp16.
// ---------------------------------------------------------------------------
#define N_X4  1048576
#define N_WQ4 1048576
#define N_WK4 262144
#define N_WV4 262144
#define N_WO4 1048576
#define N_ALL4 (N_X4 + N_WQ4 + N_WK4 + N_WV4 + N_WO4)

__global__ __launch_bounds__(256) void split_all(const float* __restrict__ X,
                                                 const float* __restrict__ Wq,
                                                 const float* __restrict__ Wk,
                                                 const float* __restrict__ Wv,
                                                 const float* __restrict__ Wo)
{
    const int i = blockIdx.x * 256 + threadIdx.x;
    const float* src;
    __half* hi;
    int off;
    bool do_split = false;
    if (i < N_X4)                       { src = X;  hi = g_Xh; off = i; do_split = true; }
    else if (i < N_X4 + N_WQ4)          { src = Wq; hi = g_Wq; off = i - N_X4; }
    else if (i < N_X4 + N_WQ4 + N_WK4)  { src = Wk; hi = g_Wk; off = i - N_X4 - N_WQ4; }
    else if (i < N_X4 + N_WQ4 + N_WK4 + N_WV4)
                                        { src = Wv; hi = g_Wv; off = i - N_X4 - N_WQ4 - N_WK4; }
    else                                { src = Wo; hi = g_Wo; off = i - N_X4 - N_WQ4 - N_WK4 - N_WV4; }

    float4 v = ((const float4*)src)[off];
    float f[4] = {v.x, v.y, v.z, v.w};
    __half h[4];
#pragma unroll
    for (int k = 0; k < 4; ++k) h[k] = __float2half_rn(f[k]);
    *(uint64_t*)(hi + 4 * off) = *(uint64_t*)h;
    if (do_split) {
        __half l[4];
#pragma unroll
        for (int k = 0; k < 4; ++k) l[k] = __float2half_rn(f[k] - __half2float(h[k]));
        *(uint64_t*)(g_Xl + 4 * off) = *(uint64_t*)l;
    }
}

// ---------------------------------------------------------------------------
// 128x128 fp16 HMMA GEMM, K-tile 64, cp.async pipeline.
// MODE 0 (fused QKV, 2-stage): A = Xh+Xl (2-term), B single; RoPE fused into
//   the Q/K epilogue (warp tile == one head; rotate_half partner in-thread).
// MODE 1 (O proj, 3-stage):    A = Ch (1-term), B = Wo.
// ---------------------------------------------------------------------------
#define T64_H 9216
#define T64_B (T64_H * 2)

template <int MODE>
__global__ __launch_bounds__(256) void hgemm7_k(const float* __restrict__ bq,
                                                const float* __restrict__ bk,
                                                const float* __restrict__ bv,
                                                float* __restrict__ outp)
{
    constexpr int NTERMS = (MODE == 0) ? 2 : 1;
    constexpr int NTILES = NTERMS + 1;
    constexpr int NSTAGES = (MODE == 0) ? 2 : 3;
    constexpr uint32_t STAGE_B = NTILES * T64_B;
    constexpr uint32_t BOFF = NTERMS * T64_B;
    constexpr int NIT = HID / 64;

    extern __shared__ __half sm[];
    const int t = threadIdx.x, w = t >> 5, lane = t & 31;
    const int bm = blockIdx.y * 128;
    const int bn = blockIdx.x * 128;
    const int wm = (w & 3) * 32, wn = (w >> 2) * 64;

    const __half* srcs[NTILES];
    const float* bias = nullptr;
    int outsel, bcol0;
    if (MODE == 0) {
        const __half* B;
        if (bn < 2048)      { B = g_Wq; bias = bq; outsel = 0; bcol0 = bn; }
        else if (bn < 2560) { B = g_Wk; bias = bk; outsel = 1; bcol0 = bn - 2048; }
        else                { B = g_Wv; bias = bv; outsel = 2; bcol0 = bn - 2560; }
        srcs[0] = g_Xh + (size_t)bm * HID;
        srcs[1] = g_Xl + (size_t)bm * HID;
        srcs[NTERMS] = B + (size_t)bcol0 * HID;
    } else {
        outsel = 3; bcol0 = bn;
        srcs[0] = g_Ch + (size_t)bm * HID;
        srcs[NTERMS] = g_Wo + (size_t)bcol0 * HID;
    }

    const uint32_t sb = s2u(sm);
    const uint32_t a_r = lane & 15, a_c8 = (lane >> 4) << 3;
    const uint32_t b_r = ((lane >> 4) << 3) + (lane & 7), b_c8 = ((lane >> 3) & 1) << 3;

    float acc[2][8][4];
#pragma unroll
    for (int mi = 0; mi < 2; ++mi)
#pragma unroll
        for (int ni = 0; ni < 8; ++ni)
#pragma unroll
            for (int r = 0; r < 4; ++r) acc[mi][ni][r] = 0.0f;

#define ISSUE(ktv, stg)                                                              \
    {                                                                                \
        const int _kt = (ktv);                                                       \
        const uint32_t _sb0 = sb + (uint32_t)(stg) * STAGE_B;                        \
        _Pragma("unroll")                                                            \
        for (int i = 0; i < 4 * NTILES; ++i) {                                       \
            const int idx = i * 256 + t;                                             \
            const int tile = idx >> 10;                                              \
            const int rem = idx & 1023;                                              \
            const int row = rem >> 3, ch = rem & 7;                                  \
            cpa16(_sb0 + (uint32_t)(tile * T64_H + row * 72 + ch * 8) * 2,           \
                  srcs[tile] + (size_t)row * HID + _kt + ch * 8);                    \
        }                                                                            \
        asm volatile("cp.async.commit_group;" ::: "memory");                         \
    }

    ISSUE(0, 0);
    if (NSTAGES == 3) ISSUE(64, 1);

    for (int it = 0; it < NIT; ++it) {
        const int cur = it % NSTAGES;
        if (NSTAGES == 2) {
            if (it < NIT - 1) {
                ISSUE((it + 1) * 64, (it + 1) & 1);
                asm volatile("cp.async.wait_group 1;" ::: "memory");
            } else {
                asm volatile("cp.async.wait_group 0;" ::: "memory");
            }
        } else {
            if (it + 2 < NIT) {
                ISSUE((it + 2) * 64, (it + 2) % 3);
                asm volatile("cp.async.wait_group 2;" ::: "memory");
            } else if (it + 1 < NIT) {
                asm volatile("cp.async.wait_group 1;" ::: "memory");
            } else {
                asm volatile("cp.async.wait_group 0;" ::: "memory");
            }
        }
        __syncthreads();

        const uint32_t st = sb + (uint32_t)cur * STAGE_B;
#pragma unroll
        for (int ks = 0; ks < 4; ++ks) {
            const uint32_t k0 = ks * 16;
            uint32_t bf[4][4];
#pragma unroll
            for (int pi = 0; pi < 4; ++pi) {
                uint32_t off = ((wn + pi * 16 + b_r) * 72 + k0 + b_c8) * 2;
                ldsm4(bf[pi], st + BOFF + off);
            }
#pragma unroll
            for (int mi = 0; mi < 2; ++mi) {
                uint32_t ah[4], al[4];
                uint32_t off = ((wm + mi * 16 + a_r) * 72 + k0 + a_c8) * 2;
                ldsm4(ah, st + 0 * T64_B + off);
                if (NTERMS == 2) ldsm4(al, st + 1 * T64_B + off);
#pragma unroll
                for (int pi = 0; pi < 4; ++pi) {
#pragma unroll
                    for (int half = 0; half < 2; ++half) {
                        const int ni = pi * 2 + half;
                        const uint32_t B0 = bf[pi][half * 2], B1 = bf[pi][half * 2 + 1];
                        mma16816(acc[mi][ni], ah[0], ah[1], ah[2], ah[3], B0, B1);
                        if (NTERMS == 2)
                            mma16816(acc[mi][ni], al[0], al[1], al[2], al[3], B0, B1);
                    }
                }
            }
        }
        __syncthreads();
    }
#undef ISSUE

    // ------------------- Epilogue -------------------
    if (MODE == 0 && outsel <= 1) {
        // Fused RoPE for Q (split output) and K (single output).
        // Warp tile covers one head; pair (d, d+32) lives at (ni, ni+4).
#pragma unroll
        for (int mi = 0; mi < 2; ++mi) {
#pragma unroll
            for (int rr = 0; rr < 2; ++rr) {
                const int row = bm + wm + mi * 16 + (lane >> 2) + rr * 8;  // seq position
#pragma unroll
                for (int ni = 0; ni < 4; ++ni) {
                    float y1[2], y2[2];
#pragma unroll
                    for (int e = 0; e < 2; ++e) {
                        const int gcol = bcol0 + wn + ni * 8 + 2 * (lane & 3) + e;
                        const int d = gcol & 63;   // 0..31
                        const float x1 = acc[mi][ni][rr * 2 + e] + bias[gcol];
                        const float x2 = acc[mi][ni + 4][rr * 2 + e] + bias[gcol + 32];
                        const float inv_freq = powf(10000.0f, -((float)(2 * d)) / 64.0f);
                        float sn, cs;
                        sincosf((float)row * inv_freq, &sn, &cs);
                        y1[e] = x1 * cs - x2 * sn;
                        y2[e] = x2 * cs + x1 * sn;
                    }
                    const int gcol0 = bcol0 + wn + ni * 8 + 2 * (lane & 3);
                    const int head = gcol0 >> 6, d0 = gcol0 & 63;
                    const size_t base = ((size_t)head * S_LEN + row) * HD;
                    const uint32_t p1 = packhf(y1[0], y1[1]);
                    const uint32_t p2 = packhf(y2[0], y2[1]);
                    if (outsel == 0) {
                        *(uint32_t*)(g_qh + base + d0) = p1;
                        *(uint32_t*)(g_qh + base + d0 + 32) = p2;
                        *(uint32_t*)(g_ql + base + d0) =
                            packhf(y1[0] - lo_h(p1), y1[1] - hi_h(p1));
                        *(uint32_t*)(g_ql + base + d0 + 32) =
                            packhf(y2[0] - lo_h(p2), y2[1] - hi_h(p2));
                    } else {
                        *(uint32_t*)(g_kh + base + d0) = p1;
                        *(uint32_t*)(g_kh + base + d0 + 32) = p2;
                    }
                }
            }
        }
    } else {
#pragma unroll
        for (int mi = 0; mi < 2; ++mi) {
#pragma unroll
            for (int ni = 0; ni < 8; ++ni) {
                const int col = bcol0 + wn + ni * 8 + 2 * (lane & 3);
                float b0 = 0.f, b1 = 0.f;
                if (MODE == 0) { b0 = bias[col]; b1 = bias[col + 1]; }
#pragma unroll
                for (int rr = 0; rr < 2; ++rr) {
                    const int row = bm + wm + mi * 16 + (lane >> 2) + rr * 8;
                    float vx = acc[mi][ni][rr * 2 + 0] + b0;
                    float vy = acc[mi][ni][rr * 2 + 1] + b1;
                    if (outsel == 2) {
                        const int head = col >> 6, d = col & 63;
                        *(uint32_t*)(g_vh + ((size_t)head * S_LEN + row) * HD + d) =
                            packhf(vx, vy);
                    } else {
                        float2 v2 = {vx, vy};
                        *(float2*)(outp + (size_t)row * HID + col) = v2;
                    }
                }
            }
        }
    }
}

#define GEMM_SMEM0 (2 * 3 * T64_B)   // 110592 (QKV: 2 stages x 3 tiles)
#define GEMM_SMEM1 (3 * 2 * T64_B)   // 110592 (O: 3 stages x 2 tiles)

// ---------------------------------------------------------------------------
// HMMA flash attention: 2-term QK^T, single-term PV (r12 proven, 118us).
// ---------------------------------------------------------------------------
#define TILE_B 9216
#define AT_QH 0
#define AT_QL 9216
#define AT_K0 18432
#define AT_K1 27648
#define AT_V  36864
#define ATTN_SMEM 46080

__global__ __launch_bounds__(128, 3) void attn_k()
{
    extern __shared__ __half smb[];
    const uint32_t sb = s2u(smb);
    const int h = blockIdx.y;
    const int zz = blockIdx.x;
    const int qb = (zz & 1) ? (31 - (zz >> 1)) : (zz >> 1);
    const int kvh = h >> 2;

    const int t = threadIdx.x, w = t >> 5, lane = t & 31;
    const size_t kvbase = (size_t)kvh * S_LEN * HD;

#define CPT(dstoff, src)                                                            \
    {                                                                               \
        _Pragma("unroll")                                                           \
        for (int ii = 0; ii < 4; ++ii) {                                            \
            const int rem = ii * 128 + t;                                           \
            const int row = rem >> 3, ch = rem & 7;                                 \
            cpa16(sb + (dstoff) + (row * 72 + ch * 8) * 2,                          \
                  (src) + row * 64 + ch * 8);                                       \
        }                                                                           \
        asm volatile("cp.async.commit_group;" ::: "memory");                        \
    }

    CPT(AT_K0, g_kh + kvbase);

    {
        const __half* qh = g_qh + ((size_t)h * S_LEN + (size_t)qb * 64) * HD;
        const __half* ql = g_ql + ((size_t)h * S_LEN + (size_t)qb * 64) * HD;
#pragma unroll
        for (int ii = 0; ii < 4; ++ii) {
            const int i = ii * 128 + t;
            const int row = i >> 3, ch = i & 7;
            *(uint4*)((char*)smb + AT_QH + (row * 72 + ch * 8) * 2) =
                *(const uint4*)(qh + row * 64 + ch * 8);
            *(uint4*)((char*)smb + AT_QL + (row * 72 + ch * 8) * 2) =
                *(const uint4*)(ql + row * 64 + ch * 8);
        }
    }
    __syncthreads();

    const uint32_t a_r = lane & 15, a_c8 = (lane >> 4) << 3;
    const uint32_t b_r = ((lane >> 4) << 3) + (lane & 7), b_c8 = ((lane >> 3) & 1) << 3;
    uint32_t qfh[4][4], qfl[4][4];
#pragma unroll
    for (int ks = 0; ks < 4; ++ks) {
        uint32_t off = ((w * 16 + a_r) * 72 + ks * 16 + a_c8) * 2;
        ldsm4(qfh[ks], sb + AT_QH + off);
        ldsm4(qfl[ks], sb + AT_QL + off);
    }

    float oacc[8][4];
#pragma unroll
    for (int nt = 0; nt < 8; ++nt)
#pragma unroll
        for (int e = 0; e < 4; ++e) oacc[nt][e] = 0.0f;
    float m_i[2] = {-1e30f, -1e30f}, l_i[2] = {0.0f, 0.0f};

    const int grow0 = qb * 64 + w * 16 + (lane >> 2);

    for (int kb = 0; kb <= qb; ++kb) {
        const uint32_t KHB = (kb & 1) ? AT_K1 : AT_K0;
        __syncthreads();
        CPT(AT_V, g_vh + kvbase + (size_t)kb * 64 * HD);
        asm volatile("cp.async.wait_group 1;" ::: "memory");
        __syncthreads();

        float sacc[8][4];
#pragma unroll
        for (int nt = 0; nt < 8; ++nt)
#pragma unroll
            for (int e = 0; e < 4; ++e) sacc[nt][e] = 0.0f;

#pragma unroll
        for (int ks = 0; ks < 4; ++ks) {
#pragma unroll
            for (int np = 0; np < 4; ++np) {
                uint32_t BH[4];
                uint32_t off = ((np * 16 + b_r) * 72 + ks * 16 + b_c8) * 2;
                ldsm4(BH, sb + KHB + off);
#pragma unroll
                for (int half = 0; half < 2; ++half) {
                    const int nt = np * 2 + half;
                    mma16816(sacc[nt], qfh[ks][0], qfh[ks][1], qfh[ks][2], qfh[ks][3],
                             BH[half * 2], BH[half * 2 + 1]);
                    mma16816(sacc[nt], qfl[ks][0], qfl[ks][1], qfl[ks][2], qfl[ks][3],
                             BH[half * 2], BH[half * 2 + 1]);
                }
            }
        }

        if (kb < qb) {
            const uint32_t nstage = (kb & 1) ? AT_K0 : AT_K1;
            CPT(nstage, g_kh + kvbase + (size_t)(kb + 1) * 64 * HD);
        }

        const bool diag = (kb == qb);
        float mt[2] = {-1e30f, -1e30f};
#pragma unroll
        for (int nt = 0; nt < 8; ++nt) {
#pragma unroll
            for (int e = 0; e < 4; ++e) {
                float v = sacc[nt][e] * 0.125f;
                v = fminf(fmaxf(v, -50.0f), 50.0f);
                if (diag) {
                    const int col = kb * 64 + nt * 8 + 2 * (lane & 3) + (e & 1);
                    const int row = grow0 + (e >> 1) * 8;
                    if (col > row) v = -1e30f;
                }
                sacc[nt][e] = v;
                mt[e >> 1] = fmaxf(mt[e >> 1], v);
            }
        }
#pragma unroll
        for (int o = 1; o < 4; o <<= 1) {
            mt[0] = fmaxf(mt[0], __shfl_xor_sync(0xffffffffu, mt[0], o));
            mt[1] = fmaxf(mt[1], __shfl_xor_sync(0xffffffffu, mt[1], o));
        }
        float corr[2], rs[2] = {0.0f, 0.0f};
#pragma unroll
        for (int rr = 0; rr < 2; ++rr) {
            const float mn = fmaxf(m_i[rr], mt[rr]);
            corr[rr] = __expf(m_i[rr] - mn);
            m_i[rr] = mn;
        }
#pragma unroll
        for (int nt = 0; nt < 8; ++nt)
#pragma unroll
            for (int e = 0; e < 4; ++e) {
                const float p = __expf(sacc[nt][e] - m_i[e >> 1]);
                sacc[nt][e] = p;
                rs[e >> 1] += p;
            }
#pragma unroll
        for (int o = 1; o < 4; o <<= 1) {
            rs[0] += __shfl_xor_sync(0xffffffffu, rs[0], o);
            rs[1] += __shfl_xor_sync(0xffffffffu, rs[1], o);
        }
#pragma unroll
        for (int rr = 0; rr < 2; ++rr) l_i[rr] = l_i[rr] * corr[rr] + rs[rr];
#pragma unroll
        for (int nt = 0; nt < 8; ++nt)
#pragma unroll
            for (int e = 0; e < 4; ++e) oacc[nt][e] *= corr[e >> 1];

        if (kb < qb) asm volatile("cp.async.wait_group 1;" ::: "memory");
        else         asm volatile("cp.async.wait_group 0;" ::: "memory");
        __syncthreads();

#pragma unroll
        for (int ks = 0; ks < 4; ++ks) {
            const int L = 2 * ks, R = 2 * ks + 1;
            uint32_t ph[4];
            ph[0] = packhf(sacc[L][0], sacc[L][1]);
            ph[1] = packhf(sacc[L][2], sacc[L][3]);
            ph[2] = packhf(sacc[R][0], sacc[R][1]);
            ph[3] = packhf(sacc[R][2], sacc[R][3]);
#pragma unroll
            for (int dp = 0; dp < 4; ++dp) {
                uint32_t VH4[4];
                uint32_t voff = ((ks * 16 + (lane & 7) + ((lane >> 3) & 1) * 8) * 72
                                 + dp * 16 + ((lane >> 4) << 3)) * 2;
                ldsm4t(VH4, sb + AT_V + voff);
#pragma unroll
                for (int half = 0; half < 2; ++half) {
                    const int nt = dp * 2 + half;
                    mma16816(oacc[nt], ph[0], ph[1], ph[2], ph[3],
                             VH4[half * 2], VH4[half * 2 + 1]);
                }
            }
        }
    }
#undef CPT

    const float inv0 = 1.0f / l_i[0], inv1 = 1.0f / l_i[1];
#pragma unroll
    for (int nt = 0; nt < 8; ++nt) {
#pragma unroll
        for (int rr = 0; rr < 2; ++rr) {
            const float inv = rr ? inv1 : inv0;
            const float v0 = oacc[nt][rr * 2 + 0] * inv;
            const float v1 = oacc[nt][rr * 2 + 1] * inv;
            const int srow = qb * 64 + w * 16 + (lane >> 2) + rr * 8;
            const int col = h * 64 + nt * 8 + 2 * (lane & 3);
            *(uint32_t*)(g_Ch + (size_t)srow * HID + col) = packhf(v0, v1);
        }
    }
}

// ---------------------------------------------------------------------------
// Launcher
// ---------------------------------------------------------------------------
extern "C" void kernel_launch(void* const* d_in, const int* in_sizes, int n_in,
                              void* d_out, int out_size)
{
    const float* X  = (const float*)d_in[0];
    const float* Wq = (const float*)d_in[2];
    const float* bq = (const float*)d_in[3];
    const float* Wk = (const float*)d_in[4];
    const float* bk = (const float*)d_in[5];
    const float* Wv = (const float*)d_in[6];
    const float* bv = (const float*)d_in[7];
    const float* Wo = (const float*)d_in[8];
    float* out = (float*)d_out;

    split_all<<<N_ALL4 / 256, 256>>>(X, Wq, Wk, Wv, Wo);

    cudaFuncSetAttribute(hgemm7_k<0>, cudaFuncAttributeMaxDynamicSharedMemorySize, GEMM_SMEM0);
    cudaFuncSetAttribute(hgemm7_k<1>, cudaFuncAttributeMaxDynamicSharedMemorySize, GEMM_SMEM1);

    // Fused QKV projection + RoPE (epilogue)
    hgemm7_k<0><<<dim3(24, S_LEN / 128), 256, GEMM_SMEM0>>>(bq, bk, bv, nullptr);

    cudaFuncSetAttribute(attn_k, cudaFuncAttributeMaxDynamicSharedMemorySize, ATTN_SMEM);
    attn_k<<<dim3(32, NH), 128, ATTN_SMEM>>>();

    hgemm7_k<1><<<dim3(16, S_LEN / 128), 256, GEMM_SMEM1>>>(nullptr, nullptr, nullptr, out);
}

// round 14
// speedup vs baseline: 1.0490x; 1.0490x over previous
#include <cuda_runtime.h>
#include <cuda_fp16.h>
#include <math.h>
#include <stdint.h>

#define S_LEN 2048
#define HID   2048
#define NH    32
#define NKV   8
#define HD    64

// ---------------------------------------------------------------------------
// Scratch (device globals)
// ---------------------------------------------------------------------------
__device__ float g_q[NH * S_LEN * HD];     // pre-RoPE Q fp32
__device__ float g_k[NKV * S_LEN * HD];    // pre-RoPE K fp32

__device__ __half g_Xh[S_LEN * HID], g_Xl[S_LEN * HID];   // X split (fp16 hi+lo)
__device__ __half g_Wq[HID * HID];                         // weights single fp16
__device__ __half g_Wk[NKV * HD * HID];
__device__ __half g_Wv[NKV * HD * HID];
__device__ __half g_Wo[HID * HID];
__device__ __half g_Ch[S_LEN * HID];                       // attn out single fp16

__device__ __half g_qh[NH * S_LEN * HD], g_ql[NH * S_LEN * HD];  // post-RoPE Q split
__device__ __half g_kh[NKV * S_LEN * HD];                        // K single fp16
__device__ __half g_vh[NKV * S_LEN * HD];                        // V single fp16

// ---------------------------------------------------------------------------
// PTX helpers
// ---------------------------------------------------------------------------
__device__ __forceinline__ uint32_t s2u(const void* p) {
    uint32_t a;
    asm("{ .reg .u64 t; cvta.to.shared.u64 t, %1; cvt.u32.u64 %0, t; }" : "=r"(a) : "l"(p));
    return a;
}

__device__ __forceinline__ void ldsm4(uint32_t* r, uint32_t addr) {
    asm volatile("ldmatrix.sync.aligned.m8n8.x4.shared.b16 {%0,%1,%2,%3}, [%4];"
                 : "=r"(r[0]), "=r"(r[1]), "=r"(r[2]), "=r"(r[3]) : "r"(addr));
}

__device__ __forceinline__ void ldsm4t(uint32_t* r, uint32_t addr) {
    asm volatile("ldmatrix.sync.aligned.m8n8.x4.trans.shared.b16 {%0,%1,%2,%3}, [%4];"
                 : "=r"(r[0]), "=r"(r[1]), "=r"(r[2]), "=r"(r[3]) : "r"(addr));
}

__device__ __forceinline__ void mma16816(float* d, uint32_t a0, uint32_t a1, uint32_t a2,
                                         uint32_t a3, uint32_t b0, uint32_t b1) {
    asm volatile(
        "mma.sync.aligned.m16n8k16.row.col.f32.f16.f16.f32 "
        "{%0,%1,%2,%3}, {%4,%5,%6,%7}, {%8,%9}, {%0,%1,%2,%3};"
        : "+f"(d[0]), "+f"(d[1]), "+f"(d[2]), "+f"(d[3])
        : "r"(a0), "r"(a1), "r"(a2), "r"(a3), "r"(b0), "r"(b1));
}

__device__ __forceinline__ void cpa16(uint32_t saddr, const void* g) {
    asm volatile("cp.async.cg.shared.global [%0], [%1], 16;" :: "r"(saddr), "l"(g) : "memory");
}

__device__ __forceinline__ uint32_t packhf(float lo, float hi) {
    uint32_t r;
    asm("cvt.rn.f16x2.f32 %0, %1, %2;" : "=r"(r) : "f"(hi), "f"(lo));
    return r;
}
__device__ __forceinline__ float lo_h(uint32_t p) {
    return __half2float(__ushort_as_half((unsigned short)(p & 0xFFFFu)));
}
__device__ __forceinline__ float hi_h(uint32_t p) {
    return __half2float(__ushort_as_half((unsigned short)(p >> 16)));
}

// ---------------------------------------------------------------------------
// Merged conversion, MLP=4: each thread processes 4 float4s strided by
// N_ALL4/4 (independent load->store chains for memory-level parallelism).
// ---------------------------------------------------------------------------
#define N_X4  1048576
#define N_WQ4 1048576
#define N_WK4 262144
#define N_WV4 262144
#define N_WO4 1048576
#define N_ALL4 (N_X4 + N_WQ4 + N_WK4 + N_WV4 + N_WO4)   // 3670016
#define N_STRIDE (N_ALL4 / 4)                            // 917504

__global__ __launch_bounds__(256) void split_all(const float* __restrict__ X,
                                                 const float* __restrict__ Wq,
                                                 const float* __restrict__ Wk,
                                                 const float* __restrict__ Wv,
                                                 const float* __restrict__ Wo)
{
    const int base = blockIdx.x * 256 + threadIdx.x;

    const float* srcp[4];
    __half* hip[4];
    int offp[4];
    bool splitp[4];
#pragma unroll
    for (int k = 0; k < 4; ++k) {
        const int i = base + k * N_STRIDE;
        const float* src; __half* hi; int off; bool ds = false;
        if (i < N_X4)                       { src = X;  hi = g_Xh; off = i; ds = true; }
        else if (i < N_X4 + N_WQ4)          { src = Wq; hi = g_Wq; off = i - N_X4; }
        else if (i < N_X4 + N_WQ4 + N_WK4)  { src = Wk; hi = g_Wk; off = i - N_X4 - N_WQ4; }
        else if (i < N_X4 + N_WQ4 + N_WK4 + N_WV4)
                                            { src = Wv; hi = g_Wv; off = i - N_X4 - N_WQ4 - N_WK4; }
        else                                { src = Wo; hi = g_Wo; off = i - N_X4 - N_WQ4 - N_WK4 - N_WV4; }
        srcp[k] = src; hip[k] = hi; offp[k] = off; splitp[k] = ds;
    }

    float4 v[4];
#pragma unroll
    for (int k = 0; k < 4; ++k) v[k] = ((const float4*)srcp[k])[offp[k]];

#pragma unroll
    for (int k = 0; k < 4; ++k) {
        float f[4] = {v[k].x, v[k].y, v[k].z, v[k].w};
        __half h[4];
#pragma unroll
        for (int e = 0; e < 4; ++e) h[e] = __float2half_rn(f[e]);
        *(uint64_t*)(hip[k] + 4 * offp[k]) = *(uint64_t*)h;
        if (splitp[k]) {
            __half l[4];
#pragma unroll
            for (int e = 0; e < 4; ++e) l[e] = __float2half_rn(f[e] - __half2float(h[e]));
            *(uint64_t*)(g_Xl + 4 * offp[k]) = *(uint64_t*)l;
        }
    }
}

// ---------------------------------------------------------------------------
// 128x128 fp16 HMMA GEMM, K-tile 64, 2-stage cp.async (r11/r12 proven).
// MODE 0 (fused QKV): A = Xh+Xl (2-term), B single.  3 tiles/stage, 110.6 KB.
// MODE 1 (O proj):    A = Ch (1-term),   B = Wo.     2 tiles/stage,  73.7 KB.
// ---------------------------------------------------------------------------
#define T64_H 9216
#define T64_B (T64_H * 2)

template <int MODE>
__global__ __launch_bounds__(256) void hgemm6_k(const float* __restrict__ bq,
                                                const float* __restrict__ bk,
                                                const float* __restrict__ bv,
                                                float* __restrict__ outp)
{
    constexpr int NTERMS = (MODE == 0) ? 2 : 1;
    constexpr int NTILES = NTERMS + 1;
    constexpr uint32_t STAGE_B = NTILES * T64_B;
    constexpr uint32_t BOFF = NTERMS * T64_B;

    extern __shared__ __half sm[];
    const int t = threadIdx.x, w = t >> 5, lane = t & 31;
    const int bm = blockIdx.y * 128;
    const int bn = blockIdx.x * 128;
    const int wm = (w & 3) * 32, wn = (w >> 2) * 64;

    const __half* srcs[NTILES];
    const float* bias = nullptr;
    int outsel, bcol0;
    if (MODE == 0) {
        const __half* B;
        if (bn < 2048)      { B = g_Wq; bias = bq; outsel = 0; bcol0 = bn; }
        else if (bn < 2560) { B = g_Wk; bias = bk; outsel = 1; bcol0 = bn - 2048; }
        else                { B = g_Wv; bias = bv; outsel = 2; bcol0 = bn - 2560; }
        srcs[0] = g_Xh + (size_t)bm * HID;
        srcs[1] = g_Xl + (size_t)bm * HID;
        srcs[NTERMS] = B + (size_t)bcol0 * HID;
    } else {
        outsel = 3; bcol0 = bn;
        srcs[0] = g_Ch + (size_t)bm * HID;
        srcs[NTERMS] = g_Wo + (size_t)bcol0 * HID;
    }

    const uint32_t sb = s2u(sm);
    const uint32_t a_r = lane & 15, a_c8 = (lane >> 4) << 3;
    const uint32_t b_r = ((lane >> 4) << 3) + (lane & 7), b_c8 = ((lane >> 3) & 1) << 3;

    float acc[2][8][4];
#pragma unroll
    for (int mi = 0; mi < 2; ++mi)
#pragma unroll
        for (int ni = 0; ni < 8; ++ni)
#pragma unroll
            for (int r = 0; r < 4; ++r) acc[mi][ni][r] = 0.0f;

#define ISSUE(ktv, stg)                                                              \
    {                                                                                \
        const int _kt = (ktv);                                                       \
        const uint32_t _sb0 = sb + (uint32_t)(stg) * STAGE_B;                        \
        _Pragma("unroll")                                                            \
        for (int i = 0; i < 4 * NTILES; ++i) {                                       \
            const int idx = i * 256 + t;                                             \
            const int tile = idx >> 10;                                              \
            const int rem = idx & 1023;                                              \
            const int row = rem >> 3, ch = rem & 7;                                  \
            cpa16(_sb0 + (uint32_t)(tile * T64_H + row * 72 + ch * 8) * 2,           \
                  srcs[tile] + (size_t)row * HID + _kt + ch * 8);                    \
        }                                                                            \
        asm volatile("cp.async.commit_group;" ::: "memory");                         \
    }

    ISSUE(0, 0);

    for (int it = 0; it < HID / 64; ++it) {
        const int cur = it & 1;
        if (it < HID / 64 - 1) {
            ISSUE((it + 1) * 64, cur ^ 1);
            asm volatile("cp.async.wait_group 1;" ::: "memory");
        } else {
            asm volatile("cp.async.wait_group 0;" ::: "memory");
        }
        __syncthreads();

        const uint32_t st = sb + (uint32_t)cur * STAGE_B;
#pragma unroll
        for (int ks = 0; ks < 4; ++ks) {
            const uint32_t k0 = ks * 16;
            uint32_t bf[4][4];
#pragma unroll
            for (int pi = 0; pi < 4; ++pi) {
                uint32_t off = ((wn + pi * 16 + b_r) * 72 + k0 + b_c8) * 2;
                ldsm4(bf[pi], st + BOFF + off);
            }
#pragma unroll
            for (int mi = 0; mi < 2; ++mi) {
                uint32_t ah[4], al[4];
                uint32_t off = ((wm + mi * 16 + a_r) * 72 + k0 + a_c8) * 2;
                ldsm4(ah, st + 0 * T64_B + off);
                if (NTERMS == 2) ldsm4(al, st + 1 * T64_B + off);
#pragma unroll
                for (int pi = 0; pi < 4; ++pi) {
#pragma unroll
                    for (int half = 0; half < 2; ++half) {
                        const int ni = pi * 2 + half;
                        const uint32_t B0 = bf[pi][half * 2], B1 = bf[pi][half * 2 + 1];
                        mma16816(acc[mi][ni], ah[0], ah[1], ah[2], ah[3], B0, B1);
                        if (NTERMS == 2)
                            mma16816(acc[mi][ni], al[0], al[1], al[2], al[3], B0, B1);
                    }
                }
            }
        }
        __syncthreads();
    }
#undef ISSUE

#pragma unroll
    for (int mi = 0; mi < 2; ++mi) {
#pragma unroll
        for (int ni = 0; ni < 8; ++ni) {
            const int lcol = wn + ni * 8 + 2 * (lane & 3);
            const int col = bcol0 + lcol;
            float b0 = 0.f, b1 = 0.f;
            if (MODE == 0) { b0 = bias[col]; b1 = bias[col + 1]; }
#pragma unroll
            for (int rr = 0; rr < 2; ++rr) {
                const int row = bm + wm + mi * 16 + (lane >> 2) + rr * 8;
                float vx = acc[mi][ni][rr * 2 + 0] + b0;
                float vy = acc[mi][ni][rr * 2 + 1] + b1;
                if (outsel == 0 || outsel == 1) {
                    const int head = col >> 6, d = col & 63;
                    float* dst = (outsel == 0) ? g_q : g_k;
                    float2 v2 = {vx, vy};
                    *(float2*)(dst + ((size_t)head * S_LEN + row) * HD + d) = v2;
                } else if (outsel == 2) {
                    const int head = col >> 6, d = col & 63;
                    *(uint32_t*)(g_vh + ((size_t)head * S_LEN + row) * HD + d) = packhf(vx, vy);
                } else {
                    float2 v2 = {vx, vy};
                    *(float2*)(outp + (size_t)row * HID + col) = v2;
                }
            }
        }
    }
}

#define GEMM_SMEM0 (2 * 3 * T64_B)
#define GEMM_SMEM1 (2 * 2 * T64_B)

// ---------------------------------------------------------------------------
// RoPE: Q -> fp16 hi/lo split; K -> single fp16.
// ---------------------------------------------------------------------------
#define ROPE_Q_N (NH * S_LEN * 16)
#define ROPE_K_N (NKV * S_LEN * 16)

__global__ __launch_bounds__(256) void rope_all()
{
    int idx = blockIdx.x * 256 + threadIdx.x;
    const bool isQ = (idx < ROPE_Q_N);
    if (!isQ) idx -= ROPE_Q_N;

    const int j2 = (idx & 15) * 2;
    const int s = (idx >> 4) & (S_LEN - 1);
    const int h = idx >> 15;
    const size_t base = ((size_t)h * S_LEN + s) * HD;

    const float* src = (isQ ? g_q : g_k) + base;
    float y1[2], y2[2];
#pragma unroll
    for (int e = 0; e < 2; ++e) {
        const int j = j2 + e;
        const float inv_freq = __powf(10000.0f, -((float)(2 * j)) / 64.0f);
        float sn, cs;
        sincosf((float)s * inv_freq, &sn, &cs);
        const float x1 = src[j], x2 = src[j + 32];
        y1[e] = x1 * cs - x2 * sn;
        y2[e] = x2 * cs + x1 * sn;
    }
    const uint32_t p1 = packhf(y1[0], y1[1]);
    const uint32_t p2 = packhf(y2[0], y2[1]);
    if (isQ) {
        *(uint32_t*)(g_qh + base + j2) = p1;
        *(uint32_t*)(g_qh + base + j2 + 32) = p2;
        *(uint32_t*)(g_ql + base + j2) = packhf(y1[0] - lo_h(p1), y1[1] - hi_h(p1));
        *(uint32_t*)(g_ql + base + j2 + 32) = packhf(y2[0] - lo_h(p2), y2[1] - hi_h(p2));
    } else {
        *(uint32_t*)(g_kh + base + j2) = p1;
        *(uint32_t*)(g_kh + base + j2 + 32) = p2;
    }
}

// ---------------------------------------------------------------------------
// HMMA flash attention: 2-term QK^T, single-term PV (r12 proven, 118us).
// ---------------------------------------------------------------------------
#define TILE_B 9216
#define AT_QH 0
#define AT_QL 9216
#define AT_K0 18432
#define AT_K1 27648
#define AT_V  36864
#define ATTN_SMEM 46080

__global__ __launch_bounds__(128, 3) void attn_k()
{
    extern __shared__ __half smb[];
    const uint32_t sb = s2u(smb);
    const int h = blockIdx.y;
    const int zz = blockIdx.x;
    const int qb = (zz & 1) ? (31 - (zz >> 1)) : (zz >> 1);
    const int kvh = h >> 2;

    const int t = threadIdx.x, w = t >> 5, lane = t & 31;
    const size_t kvbase = (size_t)kvh * S_LEN * HD;

#define CPT(dstoff, src)                                                            \
    {                                                                               \
        _Pragma("unroll")                                                           \
        for (int ii = 0; ii < 4; ++ii) {                                            \
            const int rem = ii * 128 + t;                                           \
            const int row = rem >> 3, ch = rem & 7;                                 \
            cpa16(sb + (dstoff) + (row * 72 + ch * 8) * 2,                          \
                  (src) + row * 64 + ch * 8);                                       \
        }                                                                           \
        asm volatile("cp.async.commit_group;" ::: "memory");                        \
    }

    CPT(AT_K0, g_kh + kvbase);

    {
        const __half* qh = g_qh + ((size_t)h * S_LEN + (size_t)qb * 64) * HD;
        const __half* ql = g_ql + ((size_t)h * S_LEN + (size_t)qb * 64) * HD;
#pragma unroll
        for (int ii = 0; ii < 4; ++ii) {
            const int i = ii * 128 + t;
            const int row = i >> 3, ch = i & 7;
            *(uint4*)((char*)smb + AT_QH + (row * 72 + ch * 8) * 2) =
                *(const uint4*)(qh + row * 64 + ch * 8);
            *(uint4*)((char*)smb + AT_QL + (row * 72 + ch * 8) * 2) =
                *(const uint4*)(ql + row * 64 + ch * 8);
        }
    }
    __syncthreads();

    const uint32_t a_r = lane & 15, a_c8 = (lane >> 4) << 3;
    const uint32_t b_r = ((lane >> 4) << 3) + (lane & 7), b_c8 = ((lane >> 3) & 1) << 3;
    uint32_t qfh[4][4], qfl[4][4];
#pragma unroll
    for (int ks = 0; ks < 4; ++ks) {
        uint32_t off = ((w * 16 + a_r) * 72 + ks * 16 + a_c8) * 2;
        ldsm4(qfh[ks], sb + AT_QH + off);
        ldsm4(qfl[ks], sb + AT_QL + off);
    }

    float oacc[8][4];
#pragma unroll
    for (int nt = 0; nt < 8; ++nt)
#pragma unroll
        for (int e = 0; e < 4; ++e) oacc[nt][e] = 0.0f;
    float m_i[2] = {-1e30f, -1e30f}, l_i[2] = {0.0f, 0.0f};

    const int grow0 = qb * 64 + w * 16 + (lane >> 2);

    for (int kb = 0; kb <= qb; ++kb) {
        const uint32_t KHB = (kb & 1) ? AT_K1 : AT_K0;
        __syncthreads();
        CPT(AT_V, g_vh + kvbase + (size_t)kb * 64 * HD);
        asm volatile("cp.async.wait_group 1;" ::: "memory");
        __syncthreads();

        float sacc[8][4];
#pragma unroll
        for (int nt = 0; nt < 8; ++nt)
#pragma unroll
            for (int e = 0; e < 4; ++e) sacc[nt][e] = 0.0f;

#pragma unroll
        for (int ks = 0; ks < 4; ++ks) {
#pragma unroll
            for (int np = 0; np < 4; ++np) {
                uint32_t BH[4];
                uint32_t off = ((np * 16 + b_r) * 72 + ks * 16 + b_c8) * 2;
                ldsm4(BH, sb + KHB + off);
#pragma unroll
                for (int half = 0; half < 2; ++half) {
                    const int nt = np * 2 + half;
                    mma16816(sacc[nt], qfh[ks][0], qfh[ks][1], qfh[ks][2], qfh[ks][3],
                             BH[half * 2], BH[half * 2 + 1]);
                    mma16816(sacc[nt], qfl[ks][0], qfl[ks][1], qfl[ks][2], qfl[ks][3],
                             BH[half * 2], BH[half * 2 + 1]);
                }
            }
        }

        if (kb < qb) {
            const uint32_t nstage = (kb & 1) ? AT_K0 : AT_K1;
            CPT(nstage, g_kh + kvbase + (size_t)(kb + 1) * 64 * HD);
        }

        const bool diag = (kb == qb);
        float mt[2] = {-1e30f, -1e30f};
#pragma unroll
        for (int nt = 0; nt < 8; ++nt) {
#pragma unroll
            for (int e = 0; e < 4; ++e) {
                float v = sacc[nt][e] * 0.125f;
                v = fminf(fmaxf(v, -50.0f), 50.0f);
                if (diag) {
                    const int col = kb * 64 + nt * 8 + 2 * (lane & 3) + (e & 1);
                    const int row = grow0 + (e >> 1) * 8;
                    if (col > row) v = -1e30f;
                }
                sacc[nt][e] = v;
                mt[e >> 1] = fmaxf(mt[e >> 1], v);
            }
        }
#pragma unroll
        for (int o = 1; o < 4; o <<= 1) {
            mt[0] = fmaxf(mt[0], __shfl_xor_sync(0xffffffffu, mt[0], o));
            mt[1] = fmaxf(mt[1], __shfl_xor_sync(0xffffffffu, mt[1], o));
        }
        float corr[2], rs[2] = {0.0f, 0.0f};
#pragma unroll
        for (int rr = 0; rr < 2; ++rr) {
            const float mn = fmaxf(m_i[rr], mt[rr]);
            corr[rr] = __expf(m_i[rr] - mn);
            m_i[rr] = mn;
        }
#pragma unroll
        for (int nt = 0; nt < 8; ++nt)
#pragma unroll
            for (int e = 0; e < 4; ++e) {
                const float p = __expf(sacc[nt][e] - m_i[e >> 1]);
                sacc[nt][e] = p;
                rs[e >> 1] += p;
            }
#pragma unroll
        for (int o = 1; o < 4; o <<= 1) {
            rs[0] += __shfl_xor_sync(0xffffffffu, rs[0], o);
            rs[1] += __shfl_xor_sync(0xffffffffu, rs[1], o);
        }
#pragma unroll
        for (int rr = 0; rr < 2; ++rr) l_i[rr] = l_i[rr] * corr[rr] + rs[rr];
#pragma unroll
        for (int nt = 0; nt < 8; ++nt)
#pragma unroll
            for (int e = 0; e < 4; ++e) oacc[nt][e] *= corr[e >> 1];

        if (kb < qb) asm volatile("cp.async.wait_group 1;" ::: "memory");
        else         asm volatile("cp.async.wait_group 0;" ::: "memory");
        __syncthreads();

#pragma unroll
        for (int ks = 0; ks < 4; ++ks) {
            const int L = 2 * ks, R = 2 * ks + 1;
            uint32_t ph[4];
            ph[0] = packhf(sacc[L][0], sacc[L][1]);
            ph[1] = packhf(sacc[L][2], sacc[L][3]);
            ph[2] = packhf(sacc[R][0], sacc[R][1]);
            ph[3] = packhf(sacc[R][2], sacc[R][3]);
#pragma unroll
            for (int dp = 0; dp < 4; ++dp) {
                uint32_t VH4[4];
                uint32_t voff = ((ks * 16 + (lane & 7) + ((lane >> 3) & 1) * 8) * 72
                                 + dp * 16 + ((lane >> 4) << 3)) * 2;
                ldsm4t(VH4, sb + AT_V + voff);
#pragma unroll
                for (int half = 0; half < 2; ++half) {
                    const int nt = dp * 2 + half;
                    mma16816(oacc[nt], ph[0], ph[1], ph[2], ph[3],
                             VH4[half * 2], VH4[half * 2 + 1]);
                }
            }
        }
    }
#undef CPT

    const float inv0 = 1.0f / l_i[0], inv1 = 1.0f / l_i[1];
#pragma unroll
    for (int nt = 0; nt < 8; ++nt) {
#pragma unroll
        for (int rr = 0; rr < 2; ++rr) {
            const float inv = rr ? inv1 : inv0;
            const float v0 = oacc[nt][rr * 2 + 0] * inv;
            const float v1 = oacc[nt][rr * 2 + 1] * inv;
            const int srow = qb * 64 + w * 16 + (lane >> 2) + rr * 8;
            const int col = h * 64 + nt * 8 + 2 * (lane & 3);
            *(uint32_t*)(g_Ch + (size_t)srow * HID + col) = packhf(v0, v1);
        }
    }
}

// ---------------------------------------------------------------------------
// Launcher
// ---------------------------------------------------------------------------
extern "C" void kernel_launch(void* const* d_in, const int* in_sizes, int n_in,
                              void* d_out, int out_size)
{
    const float* X  = (const float*)d_in[0];
    const float* Wq = (const float*)d_in[2];
    const float* bq = (const float*)d_in[3];
    const float* Wk = (const float*)d_in[4];
    const float* bk = (const float*)d_in[5];
    const float* Wv = (const float*)d_in[6];
    const float* bv = (const float*)d_in[7];
    const float* Wo = (const float*)d_in[8];
    float* out = (float*)d_out;

    split_all<<<N_STRIDE / 256, 256>>>(X, Wq, Wk, Wv, Wo);

    cudaFuncSetAttribute(hgemm6_k<0>, cudaFuncAttributeMaxDynamicSharedMemorySize, GEMM_SMEM0);
    cudaFuncSetAttribute(hgemm6_k<1>, cudaFuncAttributeMaxDynamicSharedMemorySize, GEMM_SMEM1);

    hgemm6_k<0><<<dim3(24, S_LEN / 128), 256, GEMM_SMEM0>>>(bq, bk, bv, nullptr);

    rope_all<<<(ROPE_Q_N + ROPE_K_N) / 256, 256>>>();

    cudaFuncSetAttribute(attn_k, cudaFuncAttributeMaxDynamicSharedMemorySize, ATTN_SMEM);
    attn_k<<<dim3(32, NH), 128, ATTN_SMEM>>>();

    hgemm6_k<1><<<dim3(16, S_LEN / 128), 256, GEMM_SMEM1>>>(nullptr, nullptr, nullptr, out);
}

// round 15
// speedup vs baseline: 1.0995x; 1.0481x over previous
#include <cuda_runtime.h>
#include <cuda_fp16.h>
#include <math.h>
#include <stdint.h>

#define S_LEN 2048
#define HID   2048
#define NH    32
#define NKV   8
#define HD    64

// ---------------------------------------------------------------------------
// Scratch (device globals)
// ---------------------------------------------------------------------------
__device__ float g_q[NH * S_LEN * HD];     // pre-RoPE Q fp32
__device__ float g_k[NKV * S_LEN * HD];    // pre-RoPE K fp32

__device__ __half g_Xh[S_LEN * HID], g_Xl[S_LEN * HID];   // X split (fp16 hi+lo)
__device__ __half g_Wq[HID * HID];                         // weights single fp16
__device__ __half g_Wk[NKV * HD * HID];
__device__ __half g_Wv[NKV * HD * HID];
__device__ __half g_Wo[HID * HID];
__device__ __half g_Ch[S_LEN * HID];                       // attn out single fp16

__device__ __half g_qh[NH * S_LEN * HD];                   // post-RoPE Q single fp16
__device__ __half g_kh[NKV * S_LEN * HD];                  // K single fp16
__device__ __half g_vh[NKV * S_LEN * HD];                  // V single fp16

// ---------------------------------------------------------------------------
// PTX helpers
// ---------------------------------------------------------------------------
__device__ __forceinline__ uint32_t s2u(const void* p) {
    uint32_t a;
    asm("{ .reg .u64 t; cvta.to.shared.u64 t, %1; cvt.u32.u64 %0, t; }" : "=r"(a) : "l"(p));
    return a;
}

__device__ __forceinline__ void ldsm4(uint32_t* r, uint32_t addr) {
    asm volatile("ldmatrix.sync.aligned.m8n8.x4.shared.b16 {%0,%1,%2,%3}, [%4];"
                 : "=r"(r[0]), "=r"(r[1]), "=r"(r[2]), "=r"(r[3]) : "r"(addr));
}

__device__ __forceinline__ void ldsm4t(uint32_t* r, uint32_t addr) {
    asm volatile("ldmatrix.sync.aligned.m8n8.x4.trans.shared.b16 {%0,%1,%2,%3}, [%4];"
                 : "=r"(r[0]), "=r"(r[1]), "=r"(r[2]), "=r"(r[3]) : "r"(addr));
}

__device__ __forceinline__ void mma16816(float* d, uint32_t a0, uint32_t a1, uint32_t a2,
                                         uint32_t a3, uint32_t b0, uint32_t b1) {
    asm volatile(
        "mma.sync.aligned.m16n8k16.row.col.f32.f16.f16.f32 "
        "{%0,%1,%2,%3}, {%4,%5,%6,%7}, {%8,%9}, {%0,%1,%2,%3};"
        : "+f"(d[0]), "+f"(d[1]), "+f"(d[2]), "+f"(d[3])
        : "r"(a0), "r"(a1), "r"(a2), "r"(a3), "r"(b0), "r"(b1));
}

__device__ __forceinline__ void cpa16(uint32_t saddr, const void* g) {
    asm volatile("cp.async.cg.shared.global [%0], [%1], 16;" :: "r"(saddr), "l"(g) : "memory");
}

__device__ __forceinline__ uint32_t packhf(float lo, float hi) {
    uint32_t r;
    asm("cvt.rn.f16x2.f32 %0, %1, %2;" : "=r"(r) : "f"(hi), "f"(lo));
    return r;
}
__device__ __forceinline__ float lo_h(uint32_t p) {
    return __half2float(__ushort_as_half((unsigned short)(p & 0xFFFFu)));
}
__device__ __forceinline__ float hi_h(uint32_t p) {
    return __half2float(__ushort_as_half((unsigned short)(p >> 16)));
}

// ---------------------------------------------------------------------------
// Merged conversion, MLP=4 (r14 proven).
// ---------------------------------------------------------------------------
#define N_X4  1048576
#define N_WQ4 1048576
#define N_WK4 262144
#define N_WV4 262144
#define N_WO4 1048576
#define N_ALL4 (N_X4 + N_WQ4 + N_WK4 + N_WV4 + N_WO4)
#define N_STRIDE (N_ALL4 / 4)

__global__ __launch_bounds__(256) void split_all(const float* __restrict__ X,
                                                 const float* __restrict__ Wq,
                                                 const float* __restrict__ Wk,
                                                 const float* __restrict__ Wv,
                                                 const float* __restrict__ Wo)
{
    const int base = blockIdx.x * 256 + threadIdx.x;

    const float* srcp[4];
    __half* hip[4];
    int offp[4];
    bool splitp[4];
#pragma unroll
    for (int k = 0; k < 4; ++k) {
        const int i = base + k * N_STRIDE;
        const float* src; __half* hi; int off; bool ds = false;
        if (i < N_X4)                       { src = X;  hi = g_Xh; off = i; ds = true; }
        else if (i < N_X4 + N_WQ4)          { src = Wq; hi = g_Wq; off = i - N_X4; }
        else if (i < N_X4 + N_WQ4 + N_WK4)  { src = Wk; hi = g_Wk; off = i - N_X4 - N_WQ4; }
        else if (i < N_X4 + N_WQ4 + N_WK4 + N_WV4)
                                            { src = Wv; hi = g_Wv; off = i - N_X4 - N_WQ4 - N_WK4; }
        else                                { src = Wo; hi = g_Wo; off = i - N_X4 - N_WQ4 - N_WK4 - N_WV4; }
        srcp[k] = src; hip[k] = hi; offp[k] = off; splitp[k] = ds;
    }

    float4 v[4];
#pragma unroll
    for (int k = 0; k < 4; ++k) v[k] = ((const float4*)srcp[k])[offp[k]];

#pragma unroll
    for (int k = 0; k < 4; ++k) {
        float f[4] = {v[k].x, v[k].y, v[k].z, v[k].w};
        __half h[4];
#pragma unroll
        for (int e = 0; e < 4; ++e) h[e] = __float2half_rn(f[e]);
        *(uint64_t*)(hip[k] + 4 * offp[k]) = *(uint64_t*)h;
        if (splitp[k]) {
            __half l[4];
#pragma unroll
            for (int e = 0; e < 4; ++e) l[e] = __float2half_rn(f[e] - __half2float(h[e]));
            *(uint64_t*)(g_Xl + 4 * offp[k]) = *(uint64_t*)l;
        }
    }
}

// ---------------------------------------------------------------------------
// 128x128 fp16 HMMA GEMM, K-tile 64, 2-stage cp.async (r11/r12/r14 proven).
// MODE 0 (fused QKV): A = Xh+Xl (2-term), B single.  3 tiles/stage, 110.6 KB.
// MODE 1 (O proj):    A = Ch (1-term),   B = Wo.     2 tiles/stage,  73.7 KB.
// ---------------------------------------------------------------------------
#define T64_H 9216
#define T64_B (T64_H * 2)

template <int MODE>
__global__ __launch_bounds__(256) void hgemm6_k(const float* __restrict__ bq,
                                                const float* __restrict__ bk,
                                                const float* __restrict__ bv,
                                                float* __restrict__ outp)
{
    constexpr int NTERMS = (MODE == 0) ? 2 : 1;
    constexpr int NTILES = NTERMS + 1;
    constexpr uint32_t STAGE_B = NTILES * T64_B;
    constexpr uint32_t BOFF = NTERMS * T64_B;

    extern __shared__ __half sm[];
    const int t = threadIdx.x, w = t >> 5, lane = t & 31;
    const int bm = blockIdx.y * 128;
    const int bn = blockIdx.x * 128;
    const int wm = (w & 3) * 32, wn = (w >> 2) * 64;

    const __half* srcs[NTILES];
    const float* bias = nullptr;
    int outsel, bcol0;
    if (MODE == 0) {
        const __half* B;
        if (bn < 2048)      { B = g_Wq; bias = bq; outsel = 0; bcol0 = bn; }
        else if (bn < 2560) { B = g_Wk; bias = bk; outsel = 1; bcol0 = bn - 2048; }
        else                { B = g_Wv; bias = bv; outsel = 2; bcol0 = bn - 2560; }
        srcs[0] = g_Xh + (size_t)bm * HID;
        srcs[1] = g_Xl + (size_t)bm * HID;
        srcs[NTERMS] = B + (size_t)bcol0 * HID;
    } else {
        outsel = 3; bcol0 = bn;
        srcs[0] = g_Ch + (size_t)bm * HID;
        srcs[NTERMS] = g_Wo + (size_t)bcol0 * HID;
    }

    const uint32_t sb = s2u(sm);
    const uint32_t a_r = lane & 15, a_c8 = (lane >> 4) << 3;
    const uint32_t b_r = ((lane >> 4) << 3) + (lane & 7), b_c8 = ((lane >> 3) & 1) << 3;

    float acc[2][8][4];
#pragma unroll
    for (int mi = 0; mi < 2; ++mi)
#pragma unroll
        for (int ni = 0; ni < 8; ++ni)
#pragma unroll
            for (int r = 0; r < 4; ++r) acc[mi][ni][r] = 0.0f;

#define ISSUE(ktv, stg)                                                              \
    {                                                                                \
        const int _kt = (ktv);                                                       \
        const uint32_t _sb0 = sb + (uint32_t)(stg) * STAGE_B;                        \
        _Pragma("unroll")                                                            \
        for (int i = 0; i < 4 * NTILES; ++i) {                                       \
            const int idx = i * 256 + t;                                             \
            const int tile = idx >> 10;                                              \
            const int rem = idx & 1023;                                              \
            const int row = rem >> 3, ch = rem & 7;                                  \
            cpa16(_sb0 + (uint32_t)(tile * T64_H + row * 72 + ch * 8) * 2,           \
                  srcs[tile] + (size_t)row * HID + _kt + ch * 8);                    \
        }                                                                            \
        asm volatile("cp.async.commit_group;" ::: "memory");                         \
    }

    ISSUE(0, 0);

    for (int it = 0; it < HID / 64; ++it) {
        const int cur = it & 1;
        if (it < HID / 64 - 1) {
            ISSUE((it + 1) * 64, cur ^ 1);
            asm volatile("cp.async.wait_group 1;" ::: "memory");
        } else {
            asm volatile("cp.async.wait_group 0;" ::: "memory");
        }
        __syncthreads();

        const uint32_t st = sb + (uint32_t)cur * STAGE_B;
#pragma unroll
        for (int ks = 0; ks < 4; ++ks) {
            const uint32_t k0 = ks * 16;
            uint32_t bf[4][4];
#pragma unroll
            for (int pi = 0; pi < 4; ++pi) {
                uint32_t off = ((wn + pi * 16 + b_r) * 72 + k0 + b_c8) * 2;
                ldsm4(bf[pi], st + BOFF + off);
            }
#pragma unroll
            for (int mi = 0; mi < 2; ++mi) {
                uint32_t ah[4], al[4];
                uint32_t off = ((wm + mi * 16 + a_r) * 72 + k0 + a_c8) * 2;
                ldsm4(ah, st + 0 * T64_B + off);
                if (NTERMS == 2) ldsm4(al, st + 1 * T64_B + off);
#pragma unroll
                for (int pi = 0; pi < 4; ++pi) {
#pragma unroll
                    for (int half = 0; half < 2; ++half) {
                        const int ni = pi * 2 + half;
                        const uint32_t B0 = bf[pi][half * 2], B1 = bf[pi][half * 2 + 1];
                        mma16816(acc[mi][ni], ah[0], ah[1], ah[2], ah[3], B0, B1);
                        if (NTERMS == 2)
                            mma16816(acc[mi][ni], al[0], al[1], al[2], al[3], B0, B1);
                    }
                }
            }
        }
        __syncthreads();
    }
#undef ISSUE

#pragma unroll
    for (int mi = 0; mi < 2; ++mi) {
#pragma unroll
        for (int ni = 0; ni < 8; ++ni) {
            const int lcol = wn + ni * 8 + 2 * (lane & 3);
            const int col = bcol0 + lcol;
            float b0 = 0.f, b1 = 0.f;
            if (MODE == 0) { b0 = bias[col]; b1 = bias[col + 1]; }
#pragma unroll
            for (int rr = 0; rr < 2; ++rr) {
                const int row = bm + wm + mi * 16 + (lane >> 2) + rr * 8;
                float vx = acc[mi][ni][rr * 2 + 0] + b0;
                float vy = acc[mi][ni][rr * 2 + 1] + b1;
                if (outsel == 0 || outsel == 1) {
                    const int head = col >> 6, d = col & 63;
                    float* dst = (outsel == 0) ? g_q : g_k;
                    float2 v2 = {vx, vy};
                    *(float2*)(dst + ((size_t)head * S_LEN + row) * HD + d) = v2;
                } else if (outsel == 2) {
                    const int head = col >> 6, d = col & 63;
                    *(uint32_t*)(g_vh + ((size_t)head * S_LEN + row) * HD + d) = packhf(vx, vy);
                } else {
                    float2 v2 = {vx, vy};
                    *(float2*)(outp + (size_t)row * HID + col) = v2;
                }
            }
        }
    }
}

#define GEMM_SMEM0 (2 * 3 * T64_B)
#define GEMM_SMEM1 (2 * 2 * T64_B)

// ---------------------------------------------------------------------------
// RoPE: Q and K both -> single fp16 (identical paths, different dst).
// ---------------------------------------------------------------------------
#define ROPE_Q_N (NH * S_LEN * 16)
#define ROPE_K_N (NKV * S_LEN * 16)

__global__ __launch_bounds__(256) void rope_all()
{
    int idx = blockIdx.x * 256 + threadIdx.x;
    const bool isQ = (idx < ROPE_Q_N);
    if (!isQ) idx -= ROPE_Q_N;

    const int j2 = (idx & 15) * 2;
    const int s = (idx >> 4) & (S_LEN - 1);
    const int h = idx >> 15;
    const size_t base = ((size_t)h * S_LEN + s) * HD;

    const float* src = (isQ ? g_q : g_k) + base;
    float y1[2], y2[2];
#pragma unroll
    for (int e = 0; e < 2; ++e) {
        const int j = j2 + e;
        const float inv_freq = __powf(10000.0f, -((float)(2 * j)) / 64.0f);
        float sn, cs;
        sincosf((float)s * inv_freq, &sn, &cs);
        const float x1 = src[j], x2 = src[j + 32];
        y1[e] = x1 * cs - x2 * sn;
        y2[e] = x2 * cs + x1 * sn;
    }
    __half* dst = (isQ ? g_qh : g_kh) + base;
    *(uint32_t*)(dst + j2) = packhf(y1[0], y1[1]);
    *(uint32_t*)(dst + j2 + 32) = packhf(y2[0], y2[1]);
}

// ---------------------------------------------------------------------------
// HMMA flash attention: single-term fp16 Q,K,P,V.
// Split K/V cp.async pipeline. smem: Q | K0 | K1 | V = 36864 B, 3 CTAs/SM.
// ---------------------------------------------------------------------------
#define TILE_B 9216
#define AT_Q  0
#define AT_K0 9216
#define AT_K1 18432
#define AT_V  27648
#define ATTN_SMEM 36864

__global__ __launch_bounds__(128, 3) void attn_k()
{
    extern __shared__ __half smb[];
    const uint32_t sb = s2u(smb);
    const int h = blockIdx.y;
    const int zz = blockIdx.x;
    const int qb = (zz & 1) ? (31 - (zz >> 1)) : (zz >> 1);
    const int kvh = h >> 2;

    const int t = threadIdx.x, w = t >> 5, lane = t & 31;
    const size_t kvbase = (size_t)kvh * S_LEN * HD;

#define CPT(dstoff, src)                                                            \
    {                                                                               \
        _Pragma("unroll")                                                           \
        for (int ii = 0; ii < 4; ++ii) {                                            \
            const int rem = ii * 128 + t;                                           \
            const int row = rem >> 3, ch = rem & 7;                                 \
            cpa16(sb + (dstoff) + (row * 72 + ch * 8) * 2,                          \
                  (src) + row * 64 + ch * 8);                                       \
        }                                                                           \
        asm volatile("cp.async.commit_group;" ::: "memory");                        \
    }

    CPT(AT_K0, g_kh + kvbase);

    {
        const __half* qh = g_qh + ((size_t)h * S_LEN + (size_t)qb * 64) * HD;
#pragma unroll
        for (int ii = 0; ii < 4; ++ii) {
            const int i = ii * 128 + t;
            const int row = i >> 3, ch = i & 7;
            *(uint4*)((char*)smb + AT_Q + (row * 72 + ch * 8) * 2) =
                *(const uint4*)(qh + row * 64 + ch * 8);
        }
    }
    __syncthreads();

    const uint32_t a_r = lane & 15, a_c8 = (lane >> 4) << 3;
    const uint32_t b_r = ((lane >> 4) << 3) + (lane & 7), b_c8 = ((lane >> 3) & 1) << 3;
    uint32_t qf[4][4];
#pragma unroll
    for (int ks = 0; ks < 4; ++ks) {
        uint32_t off = ((w * 16 + a_r) * 72 + ks * 16 + a_c8) * 2;
        ldsm4(qf[ks], sb + AT_Q + off);
    }

    float oacc[8][4];
#pragma unroll
    for (int nt = 0; nt < 8; ++nt)
#pragma unroll
        for (int e = 0; e < 4; ++e) oacc[nt][e] = 0.0f;
    float m_i[2] = {-1e30f, -1e30f}, l_i[2] = {0.0f, 0.0f};

    const int grow0 = qb * 64 + w * 16 + (lane >> 2);

    for (int kb = 0; kb <= qb; ++kb) {
        const uint32_t KHB = (kb & 1) ? AT_K1 : AT_K0;
        __syncthreads();
        CPT(AT_V, g_vh + kvbase + (size_t)kb * 64 * HD);
        asm volatile("cp.async.wait_group 1;" ::: "memory");
        __syncthreads();

        // ---- S = Q K^T (single-term) ----
        float sacc[8][4];
#pragma unroll
        for (int nt = 0; nt < 8; ++nt)
#pragma unroll
            for (int e = 0; e < 4; ++e) sacc[nt][e] = 0.0f;

#pragma unroll
        for (int ks = 0; ks < 4; ++ks) {
#pragma unroll
            for (int np = 0; np < 4; ++np) {
                uint32_t BH[4];
                uint32_t off = ((np * 16 + b_r) * 72 + ks * 16 + b_c8) * 2;
                ldsm4(BH, sb + KHB + off);
#pragma unroll
                for (int half = 0; half < 2; ++half) {
                    const int nt = np * 2 + half;
                    mma16816(sacc[nt], qf[ks][0], qf[ks][1], qf[ks][2], qf[ks][3],
                             BH[half * 2], BH[half * 2 + 1]);
                }
            }
        }

        if (kb < qb) {
            const uint32_t nstage = (kb & 1) ? AT_K0 : AT_K1;
            CPT(nstage, g_kh + kvbase + (size_t)(kb + 1) * 64 * HD);
        }

        // ---- online softmax ----
        const bool diag = (kb == qb);
        float mt[2] = {-1e30f, -1e30f};
#pragma unroll
        for (int nt = 0; nt < 8; ++nt) {
#pragma unroll
            for (int e = 0; e < 4; ++e) {
                float v = sacc[nt][e] * 0.125f;
                v = fminf(fmaxf(v, -50.0f), 50.0f);
                if (diag) {
                    const int col = kb * 64 + nt * 8 + 2 * (lane & 3) + (e & 1);
                    const int row = grow0 + (e >> 1) * 8;
                    if (col > row) v = -1e30f;
                }
                sacc[nt][e] = v;
                mt[e >> 1] = fmaxf(mt[e >> 1], v);
            }
        }
#pragma unroll
        for (int o = 1; o < 4; o <<= 1) {
            mt[0] = fmaxf(mt[0], __shfl_xor_sync(0xffffffffu, mt[0], o));
            mt[1] = fmaxf(mt[1], __shfl_xor_sync(0xffffffffu, mt[1], o));
        }
        float corr[2], rs[2] = {0.0f, 0.0f};
#pragma unroll
        for (int rr = 0; rr < 2; ++rr) {
            const float mn = fmaxf(m_i[rr], mt[rr]);
            corr[rr] = __expf(m_i[rr] - mn);
            m_i[rr] = mn;
        }
#pragma unroll
        for (int nt = 0; nt < 8; ++nt)
#pragma unroll
            for (int e = 0; e < 4; ++e) {
                const float p = __expf(sacc[nt][e] - m_i[e >> 1]);
                sacc[nt][e] = p;
                rs[e >> 1] += p;
            }
#pragma unroll
        for (int o = 1; o < 4; o <<= 1) {
            rs[0] += __shfl_xor_sync(0xffffffffu, rs[0], o);
            rs[1] += __shfl_xor_sync(0xffffffffu, rs[1], o);
        }
#pragma unroll
        for (int rr = 0; rr < 2; ++rr) l_i[rr] = l_i[rr] * corr[rr] + rs[rr];
#pragma unroll
        for (int nt = 0; nt < 8; ++nt)
#pragma unroll
            for (int e = 0; e < 4; ++e) oacc[nt][e] *= corr[e >> 1];

        // ---- wait V, then PV (single-term) ----
        if (kb < qb) asm volatile("cp.async.wait_group 1;" ::: "memory");
        else         asm volatile("cp.async.wait_group 0;" ::: "memory");
        __syncthreads();

#pragma unroll
        for (int ks = 0; ks < 4; ++ks) {
            const int L = 2 * ks, R = 2 * ks + 1;
            uint32_t ph[4];
            ph[0] = packhf(sacc[L][0], sacc[L][1]);
            ph[1] = packhf(sacc[L][2], sacc[L][3]);
            ph[2] = packhf(sacc[R][0], sacc[R][1]);
            ph[3] = packhf(sacc[R][2], sacc[R][3]);
#pragma unroll
            for (int dp = 0; dp < 4; ++dp) {
                uint32_t VH4[4];
                uint32_t voff = ((ks * 16 + (lane & 7) + ((lane >> 3) & 1) * 8) * 72
                                 + dp * 16 + ((lane >> 4) << 3)) * 2;
                ldsm4t(VH4, sb + AT_V + voff);
#pragma unroll
                for (int half = 0; half < 2; ++half) {
                    const int nt = dp * 2 + half;
                    mma16816(oacc[nt], ph[0], ph[1], ph[2], ph[3],
                             VH4[half * 2], VH4[half * 2 + 1]);
                }
            }
        }
    }
#undef CPT

    const float inv0 = 1.0f / l_i[0], inv1 = 1.0f / l_i[1];
#pragma unroll
    for (int nt = 0; nt < 8; ++nt) {
#pragma unroll
        for (int rr = 0; rr < 2; ++rr) {
            const float inv = rr ? inv1 : inv0;
            const float v0 = oacc[nt][rr * 2 + 0] * inv;
            const float v1 = oacc[nt][rr * 2 + 1] * inv;
            const int srow = qb * 64 + w * 16 + (lane >> 2) + rr * 8;
            const int col = h * 64 + nt * 8 + 2 * (lane & 3);
            *(uint32_t*)(g_Ch + (size_t)srow * HID + col) = packhf(v0, v1);
        }
    }
}

// ---------------------------------------------------------------------------
// Launcher
// ---------------------------------------------------------------------------
extern "C" void kernel_launch(void* const* d_in, const int* in_sizes, int n_in,
                              void* d_out, int out_size)
{
    const float* X  = (const float*)d_in[0];
    const float* Wq = (const float*)d_in[2];
    const float* bq = (const float*)d_in[3];
    const float* Wk = (const float*)d_in[4];
    const float* bk = (const float*)d_in[5];
    const float* Wv = (const float*)d_in[6];
    const float* bv = (const float*)d_in[7];
    const float* Wo = (const float*)d_in[8];
    float* out = (float*)d_out;

    split_all<<<N_STRIDE / 256, 256>>>(X, Wq, Wk, Wv, Wo);

    cudaFuncSetAttribute(hgemm6_k<0>, cudaFuncAttributeMaxDynamicSharedMemorySize, GEMM_SMEM0);
    cudaFuncSetAttribute(hgemm6_k<1>, cudaFuncAttributeMaxDynamicSharedMemorySize, GEMM_SMEM1);

    hgemm6_k<0><<<dim3(24, S_LEN / 128), 256, GEMM_SMEM0>>>(bq, bk, bv, nullptr);

    rope_all<<<(ROPE_Q_N + ROPE_K_N) / 256, 256>>>();

    cudaFuncSetAttribute(attn_k, cudaFuncAttributeMaxDynamicSharedMemorySize, ATTN_SMEM);
    attn_k<<<dim3(32, NH), 128, ATTN_SMEM>>>();

    hgemm6_k<1><<<dim3(16, S_LEN / 128), 256, GEMM_SMEM1>>>(nullptr, nullptr, nullptr, out);
}

// round 16
// speedup vs baseline: 1.3536x; 1.2312x over previous
#include <cuda_runtime.h>
#include <cuda_fp16.h>
#include <math.h>
#include <stdint.h>

#define S_LEN 2048
#define HID   2048
#define NH    32
#define NKV   8
#define HD    64

// ---------------------------------------------------------------------------
// Scratch (device globals)
// ---------------------------------------------------------------------------
__device__ float g_q[NH * S_LEN * HD];     // pre-RoPE Q fp32
__device__ float g_k[NKV * S_LEN * HD];    // pre-RoPE K fp32

__device__ __half g_X[S_LEN * HID];                        // X single fp16
__device__ __half g_Wq[HID * HID];
__device__ __half g_Wk[NKV * HD * HID];
__device__ __half g_Wv[NKV * HD * HID];
__device__ __half g_Wo[HID * HID];
__device__ __half g_Ch[S_LEN * HID];                       // attn out single fp16

__device__ __half g_qh[NH * S_LEN * HD];                   // post-RoPE Q (pre-scaled 1/8)
__device__ __half g_kh[NKV * S_LEN * HD];                  // K single fp16
__device__ __half g_vh[NKV * S_LEN * HD];                  // V single fp16

// ---------------------------------------------------------------------------
// PTX helpers
// ---------------------------------------------------------------------------
__device__ __forceinline__ uint32_t s2u(const void* p) {
    uint32_t a;
    asm("{ .reg .u64 t; cvta.to.shared.u64 t, %1; cvt.u32.u64 %0, t; }" : "=r"(a) : "l"(p));
    return a;
}

__device__ __forceinline__ void ldsm4(uint32_t* r, uint32_t addr) {
    asm volatile("ldmatrix.sync.aligned.m8n8.x4.shared.b16 {%0,%1,%2,%3}, [%4];"
                 : "=r"(r[0]), "=r"(r[1]), "=r"(r[2]), "=r"(r[3]) : "r"(addr));
}

__device__ __forceinline__ void ldsm4t(uint32_t* r, uint32_t addr) {
    asm volatile("ldmatrix.sync.aligned.m8n8.x4.trans.shared.b16 {%0,%1,%2,%3}, [%4];"
                 : "=r"(r[0]), "=r"(r[1]), "=r"(r[2]), "=r"(r[3]) : "r"(addr));
}

__device__ __forceinline__ void mma16816(float* d, uint32_t a0, uint32_t a1, uint32_t a2,
                                         uint32_t a3, uint32_t b0, uint32_t b1) {
    asm volatile(
        "mma.sync.aligned.m16n8k16.row.col.f32.f16.f16.f32 "
        "{%0,%1,%2,%3}, {%4,%5,%6,%7}, {%8,%9}, {%0,%1,%2,%3};"
        : "+f"(d[0]), "+f"(d[1]), "+f"(d[2]), "+f"(d[3])
        : "r"(a0), "r"(a1), "r"(a2), "r"(a3), "r"(b0), "r"(b1));
}

__device__ __forceinline__ void cpa16(uint32_t saddr, const void* g) {
    asm volatile("cp.async.cg.shared.global [%0], [%1], 16;" :: "r"(saddr), "l"(g) : "memory");
}

__device__ __forceinline__ uint32_t packhf(float lo, float hi) {
    uint32_t r;
    asm("cvt.rn.f16x2.f32 %0, %1, %2;" : "=r"(r) : "f"(hi), "f"(lo));
    return r;
}

// ---------------------------------------------------------------------------
// Merged fp32 -> fp16 convert for all 5 inputs, MLP=4.
// ---------------------------------------------------------------------------
#define N_X4  1048576
#define N_WQ4 1048576
#define N_WK4 262144
#define N_WV4 262144
#define N_WO4 1048576
#define N_ALL4 (N_X4 + N_WQ4 + N_WK4 + N_WV4 + N_WO4)
#define N_STRIDE (N_ALL4 / 4)

__global__ __launch_bounds__(256) void split_all(const float* __restrict__ X,
                                                 const float* __restrict__ Wq,
                                                 const float* __restrict__ Wk,
                                                 const float* __restrict__ Wv,
                                                 const float* __restrict__ Wo)
{
    const int base = blockIdx.x * 256 + threadIdx.x;

    const float* srcp[4];
    __half* hip[4];
    int offp[4];
#pragma unroll
    for (int k = 0; k < 4; ++k) {
        const int i = base + k * N_STRIDE;
        const float* src; __half* hi; int off;
        if (i < N_X4)                       { src = X;  hi = g_X;  off = i; }
        else if (i < N_X4 + N_WQ4)          { src = Wq; hi = g_Wq; off = i - N_X4; }
        else if (i < N_X4 + N_WQ4 + N_WK4)  { src = Wk; hi = g_Wk; off = i - N_X4 - N_WQ4; }
        else if (i < N_X4 + N_WQ4 + N_WK4 + N_WV4)
                                            { src = Wv; hi = g_Wv; off = i - N_X4 - N_WQ4 - N_WK4; }
        else                                { src = Wo; hi = g_Wo; off = i - N_X4 - N_WQ4 - N_WK4 - N_WV4; }
        srcp[k] = src; hip[k] = hi; offp[k] = off;
    }

    float4 v[4];
#pragma unroll
    for (int k = 0; k < 4; ++k) v[k] = ((const float4*)srcp[k])[offp[k]];

#pragma unroll
    for (int k = 0; k < 4; ++k) {
        __half h[4];
        h[0] = __float2half_rn(v[k].x);
        h[1] = __float2half_rn(v[k].y);
        h[2] = __float2half_rn(v[k].z);
        h[3] = __float2half_rn(v[k].w);
        *(uint64_t*)(hip[k] + 4 * offp[k]) = *(uint64_t*)h;
    }
}

// ---------------------------------------------------------------------------
// 128x128 single-term fp16 HMMA GEMM, K-tile 64, 2-stage cp.async.
// MODE 0: fused QKV (A = X, B in {Wq,Wk,Wv}), grid (24, 16)
// MODE 1: O projection (A = Ch, B = Wo),      grid (16, 16)
// smem: 2 stages x 2 tiles x 18432 B = 73728 B.
// ---------------------------------------------------------------------------
#define T64_H 9216
#define T64_B (T64_H * 2)
#define GSTAGE_B (2 * T64_B)
#define GEMM_SMEM (2 * GSTAGE_B)

template <int MODE>
__global__ __launch_bounds__(256) void hgemm8_k(const float* __restrict__ bq,
                                                const float* __restrict__ bk,
                                                const float* __restrict__ bv,
                                                float* __restrict__ outp)
{
    extern __shared__ __half sm[];
    const int t = threadIdx.x, w = t >> 5, lane = t & 31;
    const int bm = blockIdx.y * 128;
    const int bn = blockIdx.x * 128;
    const int wm = (w & 3) * 32, wn = (w >> 2) * 64;

    const __half* srcA;
    const __half* srcB;
    const float* bias = nullptr;
    int outsel, bcol0;
    if (MODE == 0) {
        srcA = g_X + (size_t)bm * HID;
        if (bn < 2048)      { srcB = g_Wq; bias = bq; outsel = 0; bcol0 = bn; }
        else if (bn < 2560) { srcB = g_Wk; bias = bk; outsel = 1; bcol0 = bn - 2048; }
        else                { srcB = g_Wv; bias = bv; outsel = 2; bcol0 = bn - 2560; }
        srcB += (size_t)bcol0 * HID;
    } else {
        outsel = 3; bcol0 = bn;
        srcA = g_Ch + (size_t)bm * HID;
        srcB = g_Wo + (size_t)bcol0 * HID;
    }

    const uint32_t sb = s2u(sm);
    const uint32_t a_r = lane & 15, a_c8 = (lane >> 4) << 3;
    const uint32_t b_r = ((lane >> 4) << 3) + (lane & 7), b_c8 = ((lane >> 3) & 1) << 3;

    float acc[2][8][4];
#pragma unroll
    for (int mi = 0; mi < 2; ++mi)
#pragma unroll
        for (int ni = 0; ni < 8; ++ni)
#pragma unroll
            for (int r = 0; r < 4; ++r) acc[mi][ni][r] = 0.0f;

#define ISSUE(ktv, stg)                                                              \
    {                                                                                \
        const int _kt = (ktv);                                                       \
        const uint32_t _sb0 = sb + (uint32_t)(stg) * GSTAGE_B;                       \
        _Pragma("unroll")                                                            \
        for (int i = 0; i < 8; ++i) {                                                \
            const int idx = i * 256 + t;                                             \
            const int tile = idx >> 10;                                              \
            const int rem = idx & 1023;                                              \
            const int row = rem >> 3, ch = rem & 7;                                  \
            cpa16(_sb0 + (uint32_t)(tile * T64_H + row * 72 + ch * 8) * 2,           \
                  (tile ? srcB : srcA) + (size_t)row * HID + _kt + ch * 8);          \
        }                                                                            \
        asm volatile("cp.async.commit_group;" ::: "memory");                         \
    }

    ISSUE(0, 0);

    for (int it = 0; it < HID / 64; ++it) {
        const int cur = it & 1;
        if (it < HID / 64 - 1) {
            ISSUE((it + 1) * 64, cur ^ 1);
            asm volatile("cp.async.wait_group 1;" ::: "memory");
        } else {
            asm volatile("cp.async.wait_group 0;" ::: "memory");
        }
        __syncthreads();

        const uint32_t st = sb + (uint32_t)cur * GSTAGE_B;
#pragma unroll
        for (int ks = 0; ks < 4; ++ks) {
            const uint32_t k0 = ks * 16;
            uint32_t bf[4][4];
#pragma unroll
            for (int pi = 0; pi < 4; ++pi) {
                uint32_t off = ((wn + pi * 16 + b_r) * 72 + k0 + b_c8) * 2;
                ldsm4(bf[pi], st + T64_B + off);
            }
#pragma unroll
            for (int mi = 0; mi < 2; ++mi) {
                uint32_t ah[4];
                uint32_t off = ((wm + mi * 16 + a_r) * 72 + k0 + a_c8) * 2;
                ldsm4(ah, st + off);
#pragma unroll
                for (int pi = 0; pi < 4; ++pi) {
#pragma unroll
                    for (int half = 0; half < 2; ++half) {
                        const int ni = pi * 2 + half;
                        mma16816(acc[mi][ni], ah[0], ah[1], ah[2], ah[3],
                                 bf[pi][half * 2], bf[pi][half * 2 + 1]);
                    }
                }
            }
        }
        __syncthreads();
    }
#undef ISSUE

#pragma unroll
    for (int mi = 0; mi < 2; ++mi) {
#pragma unroll
        for (int ni = 0; ni < 8; ++ni) {
            const int lcol = wn + ni * 8 + 2 * (lane & 3);
            const int col = bcol0 + lcol;
            float b0 = 0.f, b1 = 0.f;
            if (MODE == 0) { b0 = bias[col]; b1 = bias[col + 1]; }
#pragma unroll
            for (int rr = 0; rr < 2; ++rr) {
                const int row = bm + wm + mi * 16 + (lane >> 2) + rr * 8;
                float vx = acc[mi][ni][rr * 2 + 0] + b0;
                float vy = acc[mi][ni][rr * 2 + 1] + b1;
                if (outsel == 0 || outsel == 1) {
                    const int head = col >> 6, d = col & 63;
                    float* dst = (outsel == 0) ? g_q : g_k;
                    float2 v2 = {vx, vy};
                    *(float2*)(dst + ((size_t)head * S_LEN + row) * HD + d) = v2;
                } else if (outsel == 2) {
                    const int head = col >> 6, d = col & 63;
                    *(uint32_t*)(g_vh + ((size_t)head * S_LEN + row) * HD + d) = packhf(vx, vy);
                } else {
                    float2 v2 = {vx, vy};
                    *(float2*)(outp + (size_t)row * HID + col) = v2;
                }
            }
        }
    }
}

// ---------------------------------------------------------------------------
// RoPE: Q (pre-scaled by 1/8) and K -> single fp16.
// ---------------------------------------------------------------------------
#define ROPE_Q_N (NH * S_LEN * 16)
#define ROPE_K_N (NKV * S_LEN * 16)

__global__ __launch_bounds__(256) void rope_all()
{
    int idx = blockIdx.x * 256 + threadIdx.x;
    const bool isQ = (idx < ROPE_Q_N);
    if (!isQ) idx -= ROPE_Q_N;

    const int j2 = (idx & 15) * 2;
    const int s = (idx >> 4) & (S_LEN - 1);
    const int h = idx >> 15;
    const size_t base = ((size_t)h * S_LEN + s) * HD;

    const float* src = (isQ ? g_q : g_k) + base;
    const float qscale = isQ ? 0.125f : 1.0f;
    float y1[2], y2[2];
#pragma unroll
    for (int e = 0; e < 2; ++e) {
        const int j = j2 + e;
        const float inv_freq = __powf(10000.0f, -((float)(2 * j)) / 64.0f);
        float sn, cs;
        sincosf((float)s * inv_freq, &sn, &cs);
        const float x1 = src[j], x2 = src[j + 32];
        y1[e] = (x1 * cs - x2 * sn) * qscale;
        y2[e] = (x2 * cs + x1 * sn) * qscale;
    }
    __half* dst = (isQ ? g_qh : g_kh) + base;
    *(uint32_t*)(dst + j2) = packhf(y1[0], y1[1]);
    *(uint32_t*)(dst + j2 + 32) = packhf(y2[0], y2[1]);
}

// ---------------------------------------------------------------------------
// HMMA flash attention: single-term fp16 Q,K,P,V; Q pre-scaled by 1/8.
// Split K/V cp.async pipeline. smem: Q | K0 | K1 | V = 36864 B, 3 CTAs/SM.
// ---------------------------------------------------------------------------
#define TILE_B 9216
#define AT_Q  0
#define AT_K0 9216
#define AT_K1 18432
#define AT_V  27648
#define ATTN_SMEM 36864

__global__ __launch_bounds__(128, 3) void attn_k()
{
    extern __shared__ __half smb[];
    const uint32_t sb = s2u(smb);
    const int h = blockIdx.y;
    const int zz = blockIdx.x;
    const int qb = (zz & 1) ? (31 - (zz >> 1)) : (zz >> 1);
    const int kvh = h >> 2;

    const int t = threadIdx.x, w = t >> 5, lane = t & 31;
    const size_t kvbase = (size_t)kvh * S_LEN * HD;

#define CPT(dstoff, src)                                                            \
    {                                                                               \
        _Pragma("unroll")                                                           \
        for (int ii = 0; ii < 4; ++ii) {                                            \
            const int rem = ii * 128 + t;                                           \
            const int row = rem >> 3, ch = rem & 7;                                 \
            cpa16(sb + (dstoff) + (row * 72 + ch * 8) * 2,                          \
                  (src) + row * 64 + ch * 8);                                       \
        }                                                                           \
        asm volatile("cp.async.commit_group;" ::: "memory");                        \
    }

    CPT(AT_K0, g_kh + kvbase);

    {
        const __half* qh = g_qh + ((size_t)h * S_LEN + (size_t)qb * 64) * HD;
#pragma unroll
        for (int ii = 0; ii < 4; ++ii) {
            const int i = ii * 128 + t;
            const int row = i >> 3, ch = i & 7;
            *(uint4*)((char*)smb + AT_Q + (row * 72 + ch * 8) * 2) =
                *(const uint4*)(qh + row * 64 + ch * 8);
        }
    }
    __syncthreads();

    const uint32_t a_r = lane & 15, a_c8 = (lane >> 4) << 3;
    const uint32_t b_r = ((lane >> 4) << 3) + (lane & 7), b_c8 = ((lane >> 3) & 1) << 3;
    uint32_t qf[4][4];
#pragma unroll
    for (int ks = 0; ks < 4; ++ks) {
        uint32_t off = ((w * 16 + a_r) * 72 + ks * 16 + a_c8) * 2;
        ldsm4(qf[ks], sb + AT_Q + off);
    }

    float oacc[8][4];
#pragma unroll
    for (int nt = 0; nt < 8; ++nt)
#pragma unroll
        for (int e = 0; e < 4; ++e) oacc[nt][e] = 0.0f;
    float m_i[2] = {-1e30f, -1e30f}, l_i[2] = {0.0f, 0.0f};

    const int grow0 = qb * 64 + w * 16 + (lane >> 2);

    for (int kb = 0; kb <= qb; ++kb) {
        const uint32_t KHB = (kb & 1) ? AT_K1 : AT_K0;
        __syncthreads();
        CPT(AT_V, g_vh + kvbase + (size_t)kb * 64 * HD);
        asm volatile("cp.async.wait_group 1;" ::: "memory");
        __syncthreads();

        // ---- S = Q K^T (Q pre-scaled) ----
        float sacc[8][4];
#pragma unroll
        for (int nt = 0; nt < 8; ++nt)
#pragma unroll
            for (int e = 0; e < 4; ++e) sacc[nt][e] = 0.0f;

#pragma unroll
        for (int ks = 0; ks < 4; ++ks) {
#pragma unroll
            for (int np = 0; np < 4; ++np) {
                uint32_t BH[4];
                uint32_t off = ((np * 16 + b_r) * 72 + ks * 16 + b_c8) * 2;
                ldsm4(BH, sb + KHB + off);
#pragma unroll
                for (int half = 0; half < 2; ++half) {
                    const int nt = np * 2 + half;
                    mma16816(sacc[nt], qf[ks][0], qf[ks][1], qf[ks][2], qf[ks][3],
                             BH[half * 2], BH[half * 2 + 1]);
                }
            }
        }

        if (kb < qb) {
            const uint32_t nstage = (kb & 1) ? AT_K0 : AT_K1;
            CPT(nstage, g_kh + kvbase + (size_t)(kb + 1) * 64 * HD);
        }

        // ---- online softmax ----
        const bool diag = (kb == qb);
        float mt[2] = {-1e30f, -1e30f};
#pragma unroll
        for (int nt = 0; nt < 8; ++nt) {
#pragma unroll
            for (int e = 0; e < 4; ++e) {
                float v = sacc[nt][e];
                v = fminf(fmaxf(v, -50.0f), 50.0f);
                if (diag) {
                    const int col = kb * 64 + nt * 8 + 2 * (lane & 3) + (e & 1);
                    const int row = grow0 + (e >> 1) * 8;
                    if (col > row) v = -1e30f;
                }
                sacc[nt][e] = v;
                mt[e >> 1] = fmaxf(mt[e >> 1], v);
            }
        }
#pragma unroll
        for (int o = 1; o < 4; o <<= 1) {
            mt[0] = fmaxf(mt[0], __shfl_xor_sync(0xffffffffu, mt[0], o));
            mt[1] = fmaxf(mt[1], __shfl_xor_sync(0xffffffffu, mt[1], o));
        }
        float corr[2], rs[2] = {0.0f, 0.0f};
#pragma unroll
        for (int rr = 0; rr < 2; ++rr) {
            const float mn = fmaxf(m_i[rr], mt[rr]);
            corr[rr] = __expf(m_i[rr] - mn);
            m_i[rr] = mn;
        }
#pragma unroll
        for (int nt = 0; nt < 8; ++nt)
#pragma unroll
            for (int e = 0; e < 4; ++e) {
                const float p = __expf(sacc[nt][e] - m_i[e >> 1]);
                sacc[nt][e] = p;
                rs[e >> 1] += p;
            }
#pragma unroll
        for (int o = 1; o < 4; o <<= 1) {
            rs[0] += __shfl_xor_sync(0xffffffffu, rs[0], o);
            rs[1] += __shfl_xor_sync(0xffffffffu, rs[1], o);
        }
#pragma unroll
        for (int rr = 0; rr < 2; ++rr) l_i[rr] = l_i[rr] * corr[rr] + rs[rr];
#pragma unroll
        for (int nt = 0; nt < 8; ++nt)
#pragma unroll
            for (int e = 0; e < 4; ++e) oacc[nt][e] *= corr[e >> 1];

        // ---- wait V, then PV ----
        if (kb < qb) asm volatile("cp.async.wait_group 1;" ::: "memory");
        else         asm volatile("cp.async.wait_group 0;" ::: "memory");
        __syncthreads();

#pragma unroll
        for (int ks = 0; ks < 4; ++ks) {
            const int L = 2 * ks, R = 2 * ks + 1;
            uint32_t ph[4];
            ph[0] = packhf(sacc[L][0], sacc[L][1]);
            ph[1] = packhf(sacc[L][2], sacc[L][3]);
            ph[2] = packhf(sacc[R][0], sacc[R][1]);
            ph[3] = packhf(sacc[R][2], sacc[R][3]);
#pragma unroll
            for (int dp = 0; dp < 4; ++dp) {
                uint32_t VH4[4];
                uint32_t voff = ((ks * 16 + (lane & 7) + ((lane >> 3) & 1) * 8) * 72
                                 + dp * 16 + ((lane >> 4) << 3)) * 2;
                ldsm4t(VH4, sb + AT_V + voff);
#pragma unroll
                for (int half = 0; half < 2; ++half) {
                    const int nt = dp * 2 + half;
                    mma16816(oacc[nt], ph[0], ph[1], ph[2], ph[3],
                             VH4[half * 2], VH4[half * 2 + 1]);
                }
            }
        }
    }
#undef CPT

    const float inv0 = 1.0f / l_i[0], inv1 = 1.0f / l_i[1];
#pragma unroll
    for (int nt = 0; nt < 8; ++nt) {
#pragma unroll
        for (int rr = 0; rr < 2; ++rr) {
            const float inv = rr ? inv1 : inv0;
            const float v0 = oacc[nt][rr * 2 + 0] * inv;
            const float v1 = oacc[nt][rr * 2 + 1] * inv;
            const int srow = qb * 64 + w * 16 + (lane >> 2) + rr * 8;
            const int col = h * 64 + nt * 8 + 2 * (lane & 3);
            *(uint32_t*)(g_Ch + (size_t)srow * HID + col) = packhf(v0, v1);
        }
    }
}

// ---------------------------------------------------------------------------
// Launcher
// ---------------------------------------------------------------------------
extern "C" void kernel_launch(void* const* d_in, const int* in_sizes, int n_in,
                              void* d_out, int out_size)
{
    const float* X  = (const float*)d_in[0];
    const float* Wq = (const float*)d_in[2];
    const float* bq = (const float*)d_in[3];
    const float* Wk = (const float*)d_in[4];
    const float* bk = (const float*)d_in[5];
    const float* Wv = (const float*)d_in[6];
    const float* bv = (const float*)d_in[7];
    const float* Wo = (const float*)d_in[8];
    float* out = (float*)d_out;

    split_all<<<N_STRIDE / 256, 256>>>(X, Wq, Wk, Wv, Wo);

    cudaFuncSetAttribute(hgemm8_k<0>, cudaFuncAttributeMaxDynamicSharedMemorySize, GEMM_SMEM);
    cudaFuncSetAttribute(hgemm8_k<1>, cudaFuncAttributeMaxDynamicSharedMemorySize, GEMM_SMEM);

    hgemm8_k<0><<<dim3(24, S_LEN / 128), 256, GEMM_SMEM>>>(bq, bk, bv, nullptr);

    rope_all<<<(ROPE_Q_N + ROPE_K_N) / 256, 256>>>();

    cudaFuncSetAttribute(attn_k, cudaFuncAttributeMaxDynamicSharedMemorySize, ATTN_SMEM);
    attn_k<<<dim3(32, NH), 128, ATTN_SMEM>>>();

    hgemm8_k<1><<<dim3(16, S_LEN / 128), 256, GEMM_SMEM>>>(nullptr, nullptr, nullptr, out);
}